// round 1
// baseline (speedup 1.0000x reference)
#include <cuda_runtime.h>

// Problem constants
#define N_NODES   512000
#define N_GRAPHS  256
#define NODES_PG  2000
#define NPB       500              // nodes per block (exact divisor of 2000)
#define NBLK      (N_NODES / NPB)  // 1024 blocks
#define THREADS   256

// Device-global scratch (no allocations allowed)
__device__ float g_W[64 * 64];     // combined weights, row k (0..63), col j: j<32 -> z gate, j>=32 -> h gate
__device__ float g_b[64];          // [bz | bh]
__device__ float g_Wl[32];
__device__ float g_bl;
__device__ float g_partial[NBLK];

// ---------------------------------------------------------------------------
// Prep: fold Wz[0,0]+Wz[1,0] and Wh[0,0]+Wh[1,0] (first 64 rows only; H0 = 0
// kills rows 64..95 and the whole R gate). Wz layout (2,1,96,32) row-major.
// ---------------------------------------------------------------------------
__global__ void prep_kernel(const float* __restrict__ Wz, const float* __restrict__ bz,
                            const float* __restrict__ Wh, const float* __restrict__ bh,
                            const float* __restrict__ Wl, const float* __restrict__ bl) {
    int i = blockIdx.x * blockDim.x + threadIdx.x;
    if (i < 64 * 64) {
        int k = i >> 6, j = i & 63;
        float v;
        if (j < 32) {
            v = Wz[k * 32 + j] + Wz[96 * 32 + k * 32 + j];
        } else {
            int c = j - 32;
            v = Wh[k * 32 + c] + Wh[96 * 32 + k * 32 + c];
        }
        g_W[i] = v;
    }
    if (i < 64) g_b[i] = (i < 32) ? bz[i] : bh[i - 32];
    if (i < 32) g_Wl[i] = Wl[i];
    if (i == 0) g_bl = bl[0];
}

// Overflow-safe fast gate epilogue: sigma via 1/(1+e^-a), tanh via 2/(1+e^-2a)-1
// (both map inf -> correct saturation, no inf-inf NaN).
__device__ __forceinline__ float gate_term(float az, float ah, float wl) {
    float z = __fdividef(1.0f, 1.0f + __expf(-az));
    float e = __expf(-2.0f * ah);
    float t = __fdividef(2.0f, 1.0f + e) - 1.0f;
    float H = (1.0f - z) * t;
    return wl * fmaxf(H, 0.0f);
}

// ---------------------------------------------------------------------------
// Main: each thread computes 2 nodes (n0, n0+250) fully: 64x64 GEMV with
// packed f32x2 FMA accumulators, fused gate epilogue, block partial sum.
// ---------------------------------------------------------------------------
__global__ __launch_bounds__(THREADS) void rgcn_main_kernel(const float* __restrict__ x) {
    __shared__ float sW[64 * 64];          // 16 KB
    __shared__ float sWl[32];
    __shared__ float sb[64];
    __shared__ float swarp[8];

    int tid = threadIdx.x;

    // Stage W (coalesced), biases, Wl into shared
    #pragma unroll
    for (int i = tid; i < 64 * 64; i += THREADS) sW[i] = g_W[i];
    if (tid < 64) sb[tid] = g_b[tid];
    if (tid < 32) sWl[tid] = g_Wl[tid];
    __syncthreads();

    float s = 0.0f;

    if (tid < 250) {
        const long n0 = (long)blockIdx.x * NPB + tid;
        const long n1 = n0 + 250;

        // 32 packed-f32x2 accumulators per node: acc[c] holds cols (2c, 2c+1).
        // c in [0,16): z gate; c in [16,32): h gate.
        unsigned long long acc0[32], acc1[32];
        #pragma unroll
        for (int i = 0; i < 32; i++) {
            unsigned long long bb;
            asm("mov.b64 %0, {%1, %2};" : "=l"(bb) : "f"(sb[2 * i]), "f"(sb[2 * i + 1]));
            acc0[i] = bb;
            acc1[i] = bb;
        }

        const float4* __restrict__ x0 = (const float4*)(x + n0 * 64);
        const float4* __restrict__ x1 = (const float4*)(x + n1 * 64);

        #pragma unroll 1
        for (int kk = 0; kk < 16; kk++) {
            float4 a = x0[kk];
            float4 b = x1[kk];
            const float* xa = (const float*)&a;
            const float* xb = (const float*)&b;
            #pragma unroll
            for (int sub = 0; sub < 4; sub++) {
                unsigned long long xda, xdb;
                asm("mov.b64 %0, {%1, %1};" : "=l"(xda) : "f"(xa[sub]));
                asm("mov.b64 %0, {%1, %1};" : "=l"(xdb) : "f"(xb[sub]));
                // W row for k = kk*4 + sub : 64 floats = 16x LDS.128 (broadcast)
                const ulonglong2* __restrict__ Wk2 =
                    (const ulonglong2*)(sW + (kk * 4 + sub) * 64);
                #pragma unroll
                for (int c2 = 0; c2 < 16; c2++) {
                    ulonglong2 w2 = Wk2[c2];
                    asm("fma.rn.f32x2 %0, %1, %2, %0;" : "+l"(acc0[2 * c2])     : "l"(xda), "l"(w2.x));
                    asm("fma.rn.f32x2 %0, %1, %2, %0;" : "+l"(acc1[2 * c2])     : "l"(xdb), "l"(w2.x));
                    asm("fma.rn.f32x2 %0, %1, %2, %0;" : "+l"(acc0[2 * c2 + 1]) : "l"(xda), "l"(w2.y));
                    asm("fma.rn.f32x2 %0, %1, %2, %0;" : "+l"(acc1[2 * c2 + 1]) : "l"(xdb), "l"(w2.y));
                }
            }
        }

        // Epilogue: z cols pair acc[i] with h cols acc[i+16], Wl[2i], Wl[2i+1]
        #pragma unroll
        for (int i = 0; i < 16; i++) {
            float az0a, az0b, ah0a, ah0b, az1a, az1b, ah1a, ah1b;
            asm("mov.b64 {%0, %1}, %2;" : "=f"(az0a), "=f"(az0b) : "l"(acc0[i]));
            asm("mov.b64 {%0, %1}, %2;" : "=f"(ah0a), "=f"(ah0b) : "l"(acc0[i + 16]));
            asm("mov.b64 {%0, %1}, %2;" : "=f"(az1a), "=f"(az1b) : "l"(acc1[i]));
            asm("mov.b64 {%0, %1}, %2;" : "=f"(ah1a), "=f"(ah1b) : "l"(acc1[i + 16]));
            float wl0 = sWl[2 * i], wl1 = sWl[2 * i + 1];
            s += gate_term(az0a, ah0a, wl0) + gate_term(az0b, ah0b, wl1);
            s += gate_term(az1a, ah1a, wl0) + gate_term(az1b, ah1b, wl1);
        }
        s += 2.0f * g_bl;   // per-node +bl, two nodes
    }

    // Block reduction (inactive threads contribute 0)
    #pragma unroll
    for (int o = 16; o > 0; o >>= 1) s += __shfl_xor_sync(0xffffffffu, s, o);
    if ((tid & 31) == 0) swarp[tid >> 5] = s;
    __syncthreads();
    if (tid == 0) {
        float t = 0.0f;
        #pragma unroll
        for (int w = 0; w < 8; w++) t += swarp[w];
        g_partial[blockIdx.x] = t;   // deterministic: no atomics
    }
}

// ---------------------------------------------------------------------------
// Finalize: 4 block-partials per graph -> mean
// ---------------------------------------------------------------------------
__global__ void finalize_kernel(float* __restrict__ out) {
    int g = threadIdx.x;   // 256 graphs
    float v = g_partial[4 * g] + g_partial[4 * g + 1] +
              g_partial[4 * g + 2] + g_partial[4 * g + 3];
    out[g] = v * (1.0f / (float)NODES_PG);
}

// ---------------------------------------------------------------------------
// Inputs (metadata order): 0:x 1:edge_index 2:edge_weight 3:batch
//   4:Wz 5:bz 6:Wr 7:br 8:Wh 9:bh 10:Wl 11:bl
// edge_index/edge_weight/batch/Wr/br are mathematically dead -> never read.
// ---------------------------------------------------------------------------
extern "C" void kernel_launch(void* const* d_in, const int* in_sizes, int n_in,
                              void* d_out, int out_size) {
    const float* x  = (const float*)d_in[0];
    const float* Wz = (const float*)d_in[4];
    const float* bz = (const float*)d_in[5];
    const float* Wh = (const float*)d_in[8];
    const float* bh = (const float*)d_in[9];
    const float* Wl = (const float*)d_in[10];
    const float* bl = (const float*)d_in[11];
    float* out = (float*)d_out;

    prep_kernel<<<16, 256>>>(Wz, bz, Wh, bh, Wl, bl);
    rgcn_main_kernel<<<NBLK, THREADS>>>(x);
    finalize_kernel<<<1, N_GRAPHS>>>(out);
}

// round 3
// speedup vs baseline: 3.7498x; 3.7498x over previous
#include <cuda_runtime.h>
#include <cuda_bf16.h>
#include <cstdint>

// ---------------- problem constants ----------------
#define N_NODES   512000
#define N_GRAPHS  256
#define NODES_PG  2000
#define TILE_M    256
#define NBLK      (N_NODES / TILE_M)   // 2000 CTAs, exact

// ---------------- device-global scratch (no allocations allowed) ----------------
// B fragments in exact mma.m16n8k16 per-thread order: [kstep][ntile][lane] -> 2 regs
__device__ uint2  g_Bfrag[4 * 8 * 32];
__device__ float4 g_epi[32];          // (bz_j, bh_j, wl_j, 0)
__device__ float  g_bl;
__device__ float2 g_part[NBLK];       // per-block partials (graph g0, graph g0+1)

static __device__ __forceinline__ uint32_t smem_u32(const void* p) {
    uint32_t a;
    asm("{ .reg .u64 t; cvta.to.shared.u64 t, %1; cvt.u32.u64 %0, t; }" : "=r"(a) : "l"(p));
    return a;
}

// ---------------------------------------------------------------------------
// Prep: fold Wz[0,0]+Wz[1,0], Wh[0,0]+Wh[1,0]  (H0=0 kills rows 64..95 and the
// whole R gate; W layout (2,1,96,32) row-major). Combined matrix Wc[k][n] with
// columns interleaved: n=2j -> z gate j, n=2j+1 -> h gate j.
// Pack B operand directly in m16n8k16 ".col" B-fragment thread order:
//   b0: (k0,   n)  b1: (k0+1, n)  b2: (k0+8, n)  b3: (k0+9, n)
//   k0 = 16*ks + (lane%4)*2,  n = 8*ntile + lane/4
// ---------------------------------------------------------------------------
__global__ void prep_kernel(const float* __restrict__ Wz, const float* __restrict__ bz,
                            const float* __restrict__ Wh, const float* __restrict__ bh,
                            const float* __restrict__ Wl, const float* __restrict__ bl) {
    int i = threadIdx.x;               // 1024 threads
    int lane = i & 31;
    int t    = (i >> 5) & 7;
    int ks   = i >> 8;
    int n    = 8 * t + (lane >> 2);
    int j    = n >> 1;
    int k0   = 16 * ks + (lane & 3) * 2;

    const float* Wsrc = ((n & 1) == 0) ? Wz : Wh;
    float w0 = Wsrc[(k0    ) * 32 + j] + Wsrc[3072 + (k0    ) * 32 + j];
    float w1 = Wsrc[(k0 + 1) * 32 + j] + Wsrc[3072 + (k0 + 1) * 32 + j];
    float w2 = Wsrc[(k0 + 8) * 32 + j] + Wsrc[3072 + (k0 + 8) * 32 + j];
    float w3 = Wsrc[(k0 + 9) * 32 + j] + Wsrc[3072 + (k0 + 9) * 32 + j];

    __nv_bfloat162 p0 = __floats2bfloat162_rn(w0, w1);   // low = smaller k
    __nv_bfloat162 p1 = __floats2bfloat162_rn(w2, w3);
    g_Bfrag[i] = make_uint2(*(const uint32_t*)&p0, *(const uint32_t*)&p1);

    if (i < 32) g_epi[i] = make_float4(bz[i], bh[i], Wl[i], 0.0f);
    if (i == 0) g_bl = bl[0];
}

// ---------------------------------------------------------------------------
// Main: one CTA per 256-node tile, 8 warps, each warp M=32/N=64/K=64 via
// 64x mma.sync.m16n8k16 bf16. Fused gate epilogue + graph-split reduction.
// ---------------------------------------------------------------------------
__global__ __launch_bounds__(256, 2) void rgcn_mma_kernel(const float* __restrict__ x) {
    // A tile: 256 rows x 64 bf16, row stride 72 (conflict-free for ldmatrix)
    __shared__ __align__(16) uint16_t sA[TILE_M * 72];   // 36 KB
    __shared__ uint2  sBf[4 * 8 * 32];                   // 8 KB
    __shared__ float4 sEpi[32];
    __shared__ float  sRed[16];

    const int tid = threadIdx.x;
    const int wid = tid >> 5, lane = tid & 31;

    #pragma unroll
    for (int i = 0; i < 4; i++) sBf[tid + i * 256] = g_Bfrag[tid + i * 256];
    if (tid < 32) sEpi[tid] = g_epi[tid];

    // Load x tile (64 KB fp32, fully coalesced), convert to bf16, store padded.
    const float4* __restrict__ xt = (const float4*)x + (size_t)blockIdx.x * 4096;
    #pragma unroll
    for (int i = 0; i < 16; i++) {
        int jj = tid + i * 256;                  // float4 index: row = jj/16, chunk = jj%16
        float4 v = xt[jj];
        __nv_bfloat162 q0 = __floats2bfloat162_rn(v.x, v.y);
        __nv_bfloat162 q1 = __floats2bfloat162_rn(v.z, v.w);
        int row = jj >> 4, c = jj & 15;
        *(uint2*)(sA + row * 72 + c * 4) =
            make_uint2(*(const uint32_t*)&q0, *(const uint32_t*)&q1);
    }
    __syncthreads();

    float acc[2][8][4] = {};                     // [mtile][ntile][c0..c3]

    const int m0 = wid * 32;
    // ldmatrix x4 address row: lanes 0-7 -> rows 0-7 (k+0), 8-15 -> rows 8-15 (k+0),
    // 16-23 -> rows 0-7 (k+8), 24-31 -> rows 8-15 (k+8)
    const int ldrow = m0 + (lane & 15);
    const int ldcol = (lane >> 4) * 8;
    const uint32_t aBase = smem_u32(sA);

    #pragma unroll 1
    for (int ks = 0; ks < 4; ks++) {
        uint32_t a[2][4];
        #pragma unroll
        for (int mt = 0; mt < 2; mt++) {
            uint32_t addr = aBase + (uint32_t)(((ldrow + mt * 16) * 72 + ks * 16 + ldcol) * 2);
            asm volatile("ldmatrix.sync.aligned.m8n8.x4.shared.b16 {%0,%1,%2,%3}, [%4];"
                         : "=r"(a[mt][0]), "=r"(a[mt][1]), "=r"(a[mt][2]), "=r"(a[mt][3])
                         : "r"(addr));
        }
        uint2 bfr[8];
        #pragma unroll
        for (int t = 0; t < 8; t++) bfr[t] = sBf[ks * 256 + t * 32 + lane];

        #pragma unroll
        for (int mt = 0; mt < 2; mt++) {
            #pragma unroll
            for (int t = 0; t < 8; t++) {
                asm volatile(
                    "mma.sync.aligned.m16n8k16.row.col.f32.bf16.bf16.f32 "
                    "{%0,%1,%2,%3}, {%4,%5,%6,%7}, {%8,%9}, {%0,%1,%2,%3};"
                    : "+f"(acc[mt][t][0]), "+f"(acc[mt][t][1]),
                      "+f"(acc[mt][t][2]), "+f"(acc[mt][t][3])
                    : "r"(a[mt][0]), "r"(a[mt][1]), "r"(a[mt][2]), "r"(a[mt][3]),
                      "r"(bfr[t].x), "r"(bfr[t].y));
            }
        }
    }

    // Epilogue. acc cols: c0/c1 = (row, 2j), (row, 2j+1); c2/c3 = row+8.
    // j = 4*ntile + lane%4. H = (1-sigmoid(az))*tanh(ah) = u(1-v)/((1+u)(1+v)),
    // u = e^-az, v = e^-2ah; relu sign follows tanh -> fmaxf is exact.
    float rs[4] = {0.f, 0.f, 0.f, 0.f};          // [mt*2 + rowhalf]
    #pragma unroll
    for (int t = 0; t < 8; t++) {
        float4 e = sEpi[4 * t + (lane & 3)];
        #pragma unroll
        for (int mt = 0; mt < 2; mt++) {
            #pragma unroll
            for (int h = 0; h < 2; h++) {
                float az = acc[mt][t][2 * h]     + e.x;
                float ah = acc[mt][t][2 * h + 1] + e.y;
                float u = __expf(-az);
                float v = __expf(-2.0f * ah);
                float H = __fdividef(u * (1.0f - v), (1.0f + u) * (1.0f + v));
                rs[mt * 2 + h] += e.z * fmaxf(H, 0.0f);
            }
        }
    }
    // Each node's 32 j-terms are spread over the 4 lanes of a lane%4 group.
    #pragma unroll
    for (int i = 0; i < 4; i++) {
        rs[i] += __shfl_xor_sync(0xffffffffu, rs[i], 1);
        rs[i] += __shfl_xor_sync(0xffffffffu, rs[i], 2);
    }

    // Graph-split partials (a 256-node tile spans at most 2 graphs).
    const int base  = blockIdx.x * TILE_M;
    const int bound = (base / NODES_PG + 1) * NODES_PG;
    float s0 = 0.f, s1 = 0.f;
    if ((lane & 3) == 0) {
        #pragma unroll
        for (int i = 0; i < 4; i++) {
            int node = base + m0 + (i >> 1) * 16 + (lane >> 2) + 8 * (i & 1);
            if (node < bound) s0 += rs[i]; else s1 += rs[i];
        }
    }
    #pragma unroll
    for (int o = 16; o > 0; o >>= 1) {
        s0 += __shfl_xor_sync(0xffffffffu, s0, o);
        s1 += __shfl_xor_sync(0xffffffffu, s1, o);
    }
    if (lane == 0) { sRed[wid] = s0; sRed[wid + 8] = s1; }
    __syncthreads();
    if (tid == 0) {
        float a = 0.f, b = 0.f;
        #pragma unroll
        for (int w = 0; w < 8; w++) { a += sRed[w]; b += sRed[w + 8]; }
        g_part[blockIdx.x] = make_float2(a, b);
    }
}

// ---------------------------------------------------------------------------
// Finalize: graph g sums its ~9 overlapping block partials (slot .x if the
// block starts inside g, else .y). Deterministic, no atomics.
// ---------------------------------------------------------------------------
__global__ void finalize_kernel(float* __restrict__ out) {
    int g = threadIdx.x;                         // 256 graphs
    int b0 = (g * NODES_PG) >> 8;
    int b1 = (g * NODES_PG + NODES_PG - 1) >> 8;
    float s = 0.0f;
    for (int b = b0; b <= b1; b++) {
        float2 p = g_part[b];
        int gb = (b * TILE_M) / NODES_PG;
        s += (gb == g) ? p.x : p.y;
    }
    out[g] = s * (1.0f / (float)NODES_PG) + g_bl;
}

// ---------------------------------------------------------------------------
// Inputs (metadata order): 0:x 1:edge_index 2:edge_weight 3:batch
//   4:Wz 5:bz 6:Wr 7:br 8:Wh 9:bh 10:Wl 11:bl
// edge_index/edge_weight/batch/Wr/br are mathematically dead -> never read.
// ---------------------------------------------------------------------------
extern "C" void kernel_launch(void* const* d_in, const int* in_sizes, int n_in,
                              void* d_out, int out_size) {
    const float* x  = (const float*)d_in[0];
    const float* Wz = (const float*)d_in[4];
    const float* bz = (const float*)d_in[5];
    const float* Wh = (const float*)d_in[8];
    const float* bh = (const float*)d_in[9];
    const float* Wl = (const float*)d_in[10];
    const float* bl = (const float*)d_in[11];
    float* out = (float*)d_out;

    prep_kernel<<<1, 1024>>>(Wz, bz, Wh, bh, Wl, bl);
    rgcn_mma_kernel<<<NBLK, 256>>>(x);
    finalize_kernel<<<1, N_GRAPHS>>>(out);
}